// round 4
// baseline (speedup 1.0000x reference)
#include <cuda_runtime.h>

#define BB 2
#define TT 50
#define UU 64
#define PP 5111
#define D4 256   // 4U
#define D2 128   // 2U
#define JJ 50    // MLP hidden
#define JP 64    // padded j-stride
#define SCH 25   // s per chunk (2 chunks)

#define NXW 160              // xw1 blocks (32 p each)
#define XP  36               // padded p-stride in transposed x tile

// ---- scratch (device globals; no allocation allowed) ----
__device__ float g_zin[BB * TT * D4];    // xt@Wk + bl
__device__ float g_G  [BB * TT * JP];    // ht @ W1[:64], padded to 64, zeros j>=50
__device__ float g_xw1[PP * JP];         // X @ W1[64:192] + b1, padded, zeros j>=50

__device__ __forceinline__ float fast_tanh(float x) {
    float r;
    asm("tanh.approx.f32 %0, %1;" : "=f"(r) : "f"(x));
    return r;
}
__device__ __forceinline__ float fast_sigmoid(float x) {
    return fmaf(fast_tanh(0.5f * x), 0.5f, 0.5f);
}

// ============================================================
// Kernel 1: Z_in[b,t,d] = sum_k xt[k]*Wk[k,d] + bl[d]
//   xt[k] = X[tgt, k mod 128] * emb2[cor, k]
// grid (25,4): x = group of 4 bt, y = 64-wide d chunk.
// ============================================================
__global__ void k_zin(const int* __restrict__ tgt, const int* __restrict__ cor,
                      const float* __restrict__ X, const float* __restrict__ emb2,
                      const float* __restrict__ Wk, const float* __restrict__ bl)
{
    __shared__ float xs[4][D4];
    __shared__ float zp[4][4][UU];
    int tid = threadIdx.x;
    int dl  = tid & 63;
    int ks  = tid >> 6;
    int d   = blockIdx.y * 64 + dl;
    int bt0 = blockIdx.x * 4;

    for (int i = tid; i < 4 * D4; i += 256) {
        int bl_ = i >> 8;
        int k   = i & (D4 - 1);
        int bt  = bt0 + bl_;
        int tg  = tgt[bt];
        int cr  = cor[bt];
        xs[bl_][k] = X[tg * D2 + (k & (D2 - 1))] * emb2[cr * D4 + k];
    }
    __syncthreads();

    float a0 = 0.f, a1 = 0.f, a2 = 0.f, a3 = 0.f;
    int k0 = ks * 64;
    #pragma unroll 8
    for (int k = k0; k < k0 + 64; k++) {
        float w = Wk[k * D4 + d];
        a0 += xs[0][k] * w;
        a1 += xs[1][k] * w;
        a2 += xs[2][k] * w;
        a3 += xs[3][k] * w;
    }
    zp[0][ks][dl] = a0;
    zp[1][ks][dl] = a1;
    zp[2][ks][dl] = a2;
    zp[3][ks][dl] = a3;
    __syncthreads();

    if (ks == 0) {
        float bv = bl[d];
        #pragma unroll
        for (int bl_ = 0; bl_ < 4; bl_++) {
            float z = zp[bl_][0][dl] + zp[bl_][1][dl]
                    + zp[bl_][2][dl] + zp[bl_][3][dl] + bv;
            g_zin[(bt0 + bl_) * D4 + d] = z;
        }
    }
}

// ============================================================
// Kernel 2 (k_work): role dispatch.
//   blocks 0..1   : LSTM recurrence (+ fused G projection)
//   blocks 2..161 : XW1 GEMM (32 p per block, reg-blocked)
// These are independent -> LSTM hides behind XW1 wave & vice versa.
// ============================================================
__global__ void __launch_bounds__(256)
k_work(const int* __restrict__ tgt, const float* __restrict__ X,
       const float* __restrict__ Wr, const float* __restrict__ W1,
       const float* __restrict__ b1)
{
    __shared__ float sbuf[11056];   // xw1: 6448 + 4608 ; lstm: 6720
    int tid = threadIdx.x;

    if (blockIdx.x < 2) {
        // ----------- LSTM role -----------
        int b = blockIdx.x;
        int d = tid;                        // 0..255
        float wr[UU];
        #pragma unroll
        for (int u = 0; u < UU; u++)
            wr[u] = Wr[u * D4 + d];

        float* hts = sbuf;                   // [TT+1][UU]  (3264)
        float* zs  = sbuf + (TT + 1) * UU;   // [D4]        (256)
        float* w1s = zs + D4;                // [UU*JJ]     (3200)

        for (int i = tid; i < UU * JJ; i += 256) w1s[i] = W1[i];

        float creg = 0.f;
        if (d < UU) hts[d] = 0.f;

        float znext = g_zin[(b * TT) * D4 + d];
        __syncthreads();

        for (int t = 0; t < TT; t++) {
            float z = znext;
            if (t < TT - 1)
                znext = g_zin[(b * TT + t + 1) * D4 + d];

            const float4* h4 = (const float4*)(hts + t * UU);
            float a0 = 0.f, a1 = 0.f, a2 = 0.f, a3 = 0.f;
            float a4 = 0.f, a5 = 0.f, a6 = 0.f, a7 = 0.f;
            #pragma unroll
            for (int u4 = 0; u4 < 16; u4 += 2) {
                float4 h0 = h4[u4];
                float4 h1 = h4[u4 + 1];
                int u = u4 * 4;
                a0 += h0.x * wr[u];
                a1 += h0.y * wr[u + 1];
                a2 += h0.z * wr[u + 2];
                a3 += h0.w * wr[u + 3];
                a4 += h1.x * wr[u + 4];
                a5 += h1.y * wr[u + 5];
                a6 += h1.z * wr[u + 6];
                a7 += h1.w * wr[u + 7];
            }
            zs[d] = z + ((a0 + a1) + (a2 + a3)) + ((a4 + a5) + (a6 + a7));
            __syncthreads();
            if (d < UU) {
                float gi = fast_sigmoid(zs[d]);
                float gf = fast_sigmoid(zs[UU + d]);
                float gg = fast_tanh(zs[2 * UU + d]);
                float go = fast_sigmoid(zs[3 * UU + d]);
                creg = gf * creg + gi * gg;
                hts[(t + 1) * UU + d] = go * fast_tanh(creg);
            }
            __syncthreads();
        }

        // fused: G[b,t,j] = sum_u h_t[u]*W1[u,j]; padded stride JP, zero j>=50
        for (int idx = tid; idx < TT * JP; idx += 256) {
            int t = idx >> 6;
            int j = idx & (JP - 1);
            float v = 0.f;
            if (j < JJ) {
                const float* h = hts + (t + 1) * UU;
                float s0 = 0.f, s1 = 0.f;
                #pragma unroll
                for (int u = 0; u < UU; u += 2) {
                    s0 += h[u]     * w1s[u * JJ + j];
                    s1 += h[u + 1] * w1s[(u + 1) * JJ + j];
                }
                v = s0 + s1;
            }
            g_G[(b * TT + t) * JP + j] = v;
        }
    } else {
        // ----------- XW1 role -----------
        // XW1[p,j] = sum_k X[p,k]*W1[64+k,j] + b1[j]
        float* w1s  = sbuf;                  // [D2*JJ + 48]  (6448, pad zeroed)
        float* xsmT = sbuf + D2 * JJ + 48;   // [D2][XP] transposed (4608)
        for (int i = tid; i < D2 * JJ; i += 256) w1s[i] = W1[UU * JJ + i];
        if (tid < 48) w1s[D2 * JJ + tid] = 0.f;

        int p0 = (int)(blockIdx.x - 2) * 32;
        // stage X transposed: xsmT[k][p_local]
        for (int i = tid; i < 32 * D2; i += 256) {
            int pl = i >> 7;
            int k  = i & (D2 - 1);
            int p  = p0 + pl;
            xsmT[k * XP + pl] = (p < PP) ? X[p * D2 + k] : 0.f;
        }
        __syncthreads();

        int w = tid >> 5;          // warp 0..7 -> p quad
        int l = tid & 31;
        int j1 = l + 32;           // may exceed 50; w1s pad covers reads
        int pq = w * 4;            // local p base

        float acc[4][2];
        float b0 = b1[l];
        float b1v = (j1 < JJ) ? b1[j1] : 0.f;
        #pragma unroll
        for (int m = 0; m < 4; m++) { acc[m][0] = b0; acc[m][1] = b1v; }

        #pragma unroll 4
        for (int k = 0; k < D2; k++) {
            float4 xv = *(const float4*)(xsmT + k * XP + pq);
            float wv0 = w1s[k * JJ + l];
            float wv1 = w1s[k * JJ + j1];      // pad-safe
            acc[0][0] += xv.x * wv0;  acc[0][1] += xv.x * wv1;
            acc[1][0] += xv.y * wv0;  acc[1][1] += xv.y * wv1;
            acc[2][0] += xv.z * wv0;  acc[2][1] += xv.z * wv1;
            acc[3][0] += xv.w * wv0;  acc[3][1] += xv.w * wv1;
        }

        #pragma unroll
        for (int m = 0; m < 4; m++) {
            int p = p0 + pq + m;
            if (p < PP) {
                g_xw1[p * JP + l] = acc[m][0];
                g_xw1[p * JP + j1] = (j1 < JJ) ? acc[m][1] : 0.f;
            }
        }
    }
}

// ============================================================
// Kernel 3 (main): 8 threads per (b,p); member q owns j in
// [8q, 8q+8) (j>=50 masked via w2=0; G/XW1 rows padded+zeroed).
// acc initialized to XW1 -> suffix-accumulate a*G -> relu -> dot W2.
// blockIdx.y = s-chunk (chunk 0 pre-accumulates t=49..25).
// ============================================================
__global__ void k_main(const int* __restrict__ tgt, const float* __restrict__ cosX,
                       const float* __restrict__ W2, const float* __restrict__ b2,
                       float* __restrict__ out)
{
    __shared__ float Gs[BB * TT * JP];   // 25.6 KB (zeros already in pad)
    __shared__ int   tg[BB * TT];
    int tid = threadIdx.x;
    for (int i = tid; i < BB * TT * JP; i += blockDim.x) Gs[i] = g_G[i];
    if (tid < BB * TT) tg[tid] = tgt[tid];
    __syncthreads();

    int grp = (blockIdx.x * blockDim.x + tid) >> 3;
    if (grp >= BB * PP) return;
    int b = grp / PP;
    int p = grp - b * PP;
    int q = tid & 7;
    int jb = q * 8;
    int ch = blockIdx.y;
    const int s_lo = ch * SCH;
    const int s_hi = s_lo + SCH - 1;

    float acc[8], w2r[8];
    {
        float4 x0 = *(const float4*)(g_xw1 + p * JP + jb);
        float4 x1 = *(const float4*)(g_xw1 + p * JP + jb + 4);
        acc[0] = x0.x; acc[1] = x0.y; acc[2] = x0.z; acc[3] = x0.w;
        acc[4] = x1.x; acc[5] = x1.y; acc[6] = x1.z; acc[7] = x1.w;
    }
    #pragma unroll
    for (int m = 0; m < 8; m++) {
        int j = jb + m;
        w2r[m] = (j < JJ) ? W2[j] : 0.f;
    }
    float bias2 = b2[0];

    // phase A (chunk 0 only): accumulate tail t = 49..25, no output
    if (ch == 0) {
        #pragma unroll 5
        for (int t = TT - 1; t > s_hi; t--) {
            float a = __ldg(&cosX[(size_t)tg[b * TT + t] * PP + p]);
            const float4* g4 = (const float4*)(Gs + (b * TT + t) * JP + jb);
            float4 g0 = g4[0], g1 = g4[1];
            acc[0] += a * g0.x; acc[1] += a * g0.y;
            acc[2] += a * g0.z; acc[3] += a * g0.w;
            acc[4] += a * g1.x; acc[5] += a * g1.y;
            acc[6] += a * g1.z; acc[7] += a * g1.w;
        }
    }

    // phase B: s = s_hi .. s_lo with output
    float a = __ldg(&cosX[(size_t)tg[b * TT + s_hi] * PP + p]);
    #pragma unroll 5
    for (int s = s_hi; s >= s_lo; s--) {
        float a_next = (s > s_lo)
            ? __ldg(&cosX[(size_t)tg[b * TT + s - 1] * PP + p]) : 0.f;

        const float4* g4 = (const float4*)(Gs + (b * TT + s) * JP + jb);
        float4 g0 = g4[0], g1 = g4[1];
        acc[0] += a * g0.x; acc[1] += a * g0.y;
        acc[2] += a * g0.z; acc[3] += a * g0.w;
        acc[4] += a * g1.x; acc[5] += a * g1.y;
        acc[6] += a * g1.z; acc[7] += a * g1.w;

        float part = 0.f;
        #pragma unroll
        for (int m = 0; m < 8; m++)
            part += fmaxf(acc[m], 0.f) * w2r[m];

        part += __shfl_xor_sync(0xffffffffu, part, 1);
        part += __shfl_xor_sync(0xffffffffu, part, 2);
        part += __shfl_xor_sync(0xffffffffu, part, 4);
        if (q == 0)
            out[(b * TT + s) * PP + p] = part + bias2;

        a = a_next;
    }
}

// ============================================================
// Launcher
// ============================================================
extern "C" void kernel_launch(void* const* d_in, const int* in_sizes, int n_in,
                              void* d_out, int out_size)
{
    const int   *tgt = nullptr, *cor = nullptr;
    const float *X = nullptr, *cosX = nullptr, *emb2 = nullptr, *Wk = nullptr;
    const float *Wr = nullptr, *bl = nullptr, *W1 = nullptr, *b1 = nullptr;
    const float *W2 = nullptr, *b2 = nullptr;

    int cnt1 = 0;
    for (int i = 0; i < n_in; i++) if (in_sizes[i] == 1) cnt1++;
    int seen1 = 0;

    for (int i = 0; i < n_in; i++) {
        int sz = in_sizes[i];
        const void* ptr = d_in[i];
        if (sz == BB * TT) {
            if (!tgt) tgt = (const int*)ptr; else cor = (const int*)ptr;
        } else if (sz == PP * PP)   cosX = (const float*)ptr;
        else if (sz == PP * D2)     X    = (const float*)ptr;
        else if (sz == D4 * D4)     Wk   = (const float*)ptr;
        else if (sz == UU * D4)     Wr   = (const float*)ptr;
        else if (sz == 2 * D4)      emb2 = (const float*)ptr;
        else if (sz == D4)          bl   = (const float*)ptr;
        else if (sz == 3 * UU * JJ) W1   = (const float*)ptr;
        else if (sz == JJ) {
            if (!b1) b1 = (const float*)ptr; else W2 = (const float*)ptr;
        } else if (sz == 1) {
            seen1++;
            if (seen1 == cnt1) b2 = (const float*)ptr;
        }
    }

    // 1) input projection (dependency of the LSTM)
    k_zin<<<dim3(25, 4), 256>>>(tgt, cor, X, emb2, Wk, bl);
    // 2) LSTM (blocks 0-1) overlapped with XW1 GEMM (blocks 2..161)
    k_work<<<2 + NXW, 256>>>(tgt, X, Wr, W1, b1);
    // 3) fused suffix-sum + MLP + octet reduce, 2 s-chunks
    int nthreads = 8 * BB * PP;                    // 81776
    int nblkx = (nthreads + 255) / 256;            // 320
    k_main<<<dim3(nblkx, 2), 256>>>(tgt, cosX, W2, b2, (float*)d_out);
}

// round 5
// speedup vs baseline: 1.0279x; 1.0279x over previous
#include <cuda_runtime.h>

#define BB 2
#define TT 50
#define UU 64
#define PP 5111
#define D4 256   // 4U
#define D2 128   // 2U
#define JJ 50    // MLP hidden
#define JP 64    // padded j-stride
#define SCH 25   // s per chunk (2 chunks)

#define NXW 160              // xw1 blocks (32 p each)
#define XP  36               // padded p-stride in transposed x tile

// ---- scratch (device globals; no allocation allowed) ----
__device__ float g_zin[BB * TT * D4];    // xt@Wk + bl
__device__ float g_G  [BB * TT * JP];    // ht @ W1[:64], padded to 64, zeros j>=50
__device__ float g_xw1[(PP + 32) * JP];  // X @ W1[64:192] + b1, padded, zeros j>=50

__device__ __forceinline__ float fast_tanh(float x) {
    float r;
    asm("tanh.approx.f32 %0, %1;" : "=f"(r) : "f"(x));
    return r;
}
__device__ __forceinline__ float fast_sigmoid(float x) {
    return fmaf(fast_tanh(0.5f * x), 0.5f, 0.5f);
}

// ============================================================
// Kernel 1: Z_in[bt,d] = sum_k xt[k]*Wk[k,d] + bl[d]
//   xt[k] = X[tgt, k mod 128] * emb2[cor, k]
// One block per bt, 1024 threads = 256 d x 4 k-splits.
// Manual 16-wide load batching forces MLP=16.
// ============================================================
__global__ void __launch_bounds__(1024)
k_zin(const int* __restrict__ tgt, const int* __restrict__ cor,
      const float* __restrict__ X, const float* __restrict__ emb2,
      const float* __restrict__ Wk, const float* __restrict__ bl)
{
    __shared__ float xs[D4];
    __shared__ float zp[4][D4];
    int tid = threadIdx.x;
    int bt  = blockIdx.x;
    int d   = tid & (D4 - 1);
    int ks  = tid >> 8;               // 0..3

    if (tid < D4) {
        int tg = tgt[bt];
        int cr = cor[bt];
        xs[tid] = X[tg * D2 + (tid & (D2 - 1))] * emb2[cr * D4 + tid];
    }
    __syncthreads();

    int k0 = ks * 64;
    float acc = 0.f;
    #pragma unroll
    for (int kk = 0; kk < 64; kk += 16) {
        float w[16];
        #pragma unroll
        for (int i = 0; i < 16; i++)
            w[i] = Wk[(k0 + kk + i) * D4 + d];   // 16 independent LDG in flight
        #pragma unroll
        for (int i = 0; i < 16; i++)
            acc += xs[k0 + kk + i] * w[i];
    }
    zp[ks][d] = acc;
    __syncthreads();

    if (ks == 0)
        g_zin[bt * D4 + d] = zp[0][d] + zp[1][d] + zp[2][d] + zp[3][d] + bl[d];
}

// ============================================================
// Kernel 2 (k_work): role dispatch.
//   blocks 0..1   : LSTM recurrence (+ fused G projection)
//   blocks 2..161 : XW1 GEMM (32 p per block, reg-blocked)
// ============================================================
__global__ void __launch_bounds__(256)
k_work(const int* __restrict__ tgt, const float* __restrict__ X,
       const float* __restrict__ Wr, const float* __restrict__ W1,
       const float* __restrict__ b1)
{
    __shared__ float sbuf[11056];   // xw1: 6448 + 4608 ; lstm: 6720
    int tid = threadIdx.x;

    if (blockIdx.x < 2) {
        // ----------- LSTM role -----------
        int b = blockIdx.x;
        int d = tid;                        // 0..255
        float wr[UU];
        #pragma unroll
        for (int u = 0; u < UU; u++)
            wr[u] = Wr[u * D4 + d];

        float* hts = sbuf;                   // [TT+1][UU]  (3264)
        float* zs  = sbuf + (TT + 1) * UU;   // [D4]        (256)
        float* w1s = zs + D4;                // [UU*JJ]     (3200)

        for (int i = tid; i < UU * JJ; i += 256) w1s[i] = W1[i];

        float creg = 0.f;
        if (d < UU) hts[d] = 0.f;

        float znext = g_zin[(b * TT) * D4 + d];
        __syncthreads();

        for (int t = 0; t < TT; t++) {
            float z = znext;
            if (t < TT - 1)
                znext = g_zin[(b * TT + t + 1) * D4 + d];

            const float4* h4 = (const float4*)(hts + t * UU);
            float a0 = 0.f, a1 = 0.f, a2 = 0.f, a3 = 0.f;
            float a4 = 0.f, a5 = 0.f, a6 = 0.f, a7 = 0.f;
            #pragma unroll
            for (int u4 = 0; u4 < 16; u4 += 2) {
                float4 h0 = h4[u4];
                float4 h1 = h4[u4 + 1];
                int u = u4 * 4;
                a0 += h0.x * wr[u];
                a1 += h0.y * wr[u + 1];
                a2 += h0.z * wr[u + 2];
                a3 += h0.w * wr[u + 3];
                a4 += h1.x * wr[u + 4];
                a5 += h1.y * wr[u + 5];
                a6 += h1.z * wr[u + 6];
                a7 += h1.w * wr[u + 7];
            }
            zs[d] = z + ((a0 + a1) + (a2 + a3)) + ((a4 + a5) + (a6 + a7));
            __syncthreads();
            if (d < UU) {
                float gi = fast_sigmoid(zs[d]);
                float gf = fast_sigmoid(zs[UU + d]);
                float gg = fast_tanh(zs[2 * UU + d]);
                float go = fast_sigmoid(zs[3 * UU + d]);
                creg = gf * creg + gi * gg;
                hts[(t + 1) * UU + d] = go * fast_tanh(creg);
            }
            __syncthreads();
        }

        // fused: G[b,t,j] = sum_u h_t[u]*W1[u,j]; padded stride JP, zero j>=50
        for (int idx = tid; idx < TT * JP; idx += 256) {
            int t = idx >> 6;
            int j = idx & (JP - 1);
            float v = 0.f;
            if (j < JJ) {
                const float* h = hts + (t + 1) * UU;
                float s0 = 0.f, s1 = 0.f;
                #pragma unroll
                for (int u = 0; u < UU; u += 2) {
                    s0 += h[u]     * w1s[u * JJ + j];
                    s1 += h[u + 1] * w1s[(u + 1) * JJ + j];
                }
                v = s0 + s1;
            }
            g_G[(b * TT + t) * JP + j] = v;
        }
    } else {
        // ----------- XW1 role -----------
        float* w1s  = sbuf;                  // [D2*JJ + 48]  (6448, pad zeroed)
        float* xsmT = sbuf + D2 * JJ + 48;   // [D2][XP] transposed (4608)
        for (int i = tid; i < D2 * JJ; i += 256) w1s[i] = W1[UU * JJ + i];
        if (tid < 48) w1s[D2 * JJ + tid] = 0.f;

        int p0 = (int)(blockIdx.x - 2) * 32;
        for (int i = tid; i < 32 * D2; i += 256) {
            int pl = i >> 7;
            int k  = i & (D2 - 1);
            int p  = p0 + pl;
            xsmT[k * XP + pl] = (p < PP) ? X[p * D2 + k] : 0.f;
        }
        __syncthreads();

        int w = tid >> 5;
        int l = tid & 31;
        int j1 = l + 32;
        int pq = w * 4;

        float acc[4][2];
        float b0 = b1[l];
        float b1v = (j1 < JJ) ? b1[j1] : 0.f;
        #pragma unroll
        for (int m = 0; m < 4; m++) { acc[m][0] = b0; acc[m][1] = b1v; }

        #pragma unroll 4
        for (int k = 0; k < D2; k++) {
            float4 xv = *(const float4*)(xsmT + k * XP + pq);
            float wv0 = w1s[k * JJ + l];
            float wv1 = w1s[k * JJ + j1];      // pad-safe
            acc[0][0] += xv.x * wv0;  acc[0][1] += xv.x * wv1;
            acc[1][0] += xv.y * wv0;  acc[1][1] += xv.y * wv1;
            acc[2][0] += xv.z * wv0;  acc[2][1] += xv.z * wv1;
            acc[3][0] += xv.w * wv0;  acc[3][1] += xv.w * wv1;
        }

        #pragma unroll
        for (int m = 0; m < 4; m++) {
            int p = p0 + pq + m;
            if (p < PP) {
                g_xw1[p * JP + l] = acc[m][0];
                g_xw1[p * JP + j1] = (j1 < JJ) ? acc[m][1] : 0.f;
            }
        }
    }
}

// ============================================================
// Kernel 3 (main): 8 threads per (b,p); member q owns j in
// [8q, 8q+8). grid = (160 p-blocks, 2 s-chunks, 2 b).
// Stage only this b's G slice (12.8KB).
// acc init = XW1 row; suffix-accumulate a*G; relu; dot W2.
// ============================================================
__global__ void __launch_bounds__(256)
k_main(const int* __restrict__ tgt, const float* __restrict__ cosX,
       const float* __restrict__ W2, const float* __restrict__ b2,
       float* __restrict__ out)
{
    __shared__ float Gs[TT * JP];   // 12.8 KB, this b only
    __shared__ int   tg[TT];
    int tid = threadIdx.x;
    int b = blockIdx.z;

    {
        const float4* src = (const float4*)(g_G + b * TT * JP);
        float4* dst = (float4*)Gs;
        for (int i = tid; i < TT * JP / 4; i += 256) dst[i] = src[i];
        if (tid < TT) tg[tid] = tgt[b * TT + tid];
    }
    __syncthreads();

    int p = blockIdx.x * 32 + (tid >> 3);
    if (p >= PP) return;
    int q = tid & 7;
    int jb = q * 8;
    int ch = blockIdx.y;
    const int s_lo = ch * SCH;
    const int s_hi = s_lo + SCH - 1;

    float acc[8], w2r[8];
    {
        float4 x0 = *(const float4*)(g_xw1 + p * JP + jb);
        float4 x1 = *(const float4*)(g_xw1 + p * JP + jb + 4);
        acc[0] = x0.x; acc[1] = x0.y; acc[2] = x0.z; acc[3] = x0.w;
        acc[4] = x1.x; acc[5] = x1.y; acc[6] = x1.z; acc[7] = x1.w;
    }
    #pragma unroll
    for (int m = 0; m < 8; m++) {
        int j = jb + m;
        w2r[m] = (j < JJ) ? W2[j] : 0.f;
    }
    float bias2 = b2[0];

    // phase A (chunk 0 only): accumulate tail t = 49..25, no output
    if (ch == 0) {
        #pragma unroll 5
        for (int t = TT - 1; t > s_hi; t--) {
            float a = __ldg(&cosX[(size_t)tg[t] * PP + p]);
            const float4* g4 = (const float4*)(Gs + t * JP + jb);
            float4 g0 = g4[0], g1 = g4[1];
            acc[0] += a * g0.x; acc[1] += a * g0.y;
            acc[2] += a * g0.z; acc[3] += a * g0.w;
            acc[4] += a * g1.x; acc[5] += a * g1.y;
            acc[6] += a * g1.z; acc[7] += a * g1.w;
        }
    }

    // phase B: s = s_hi .. s_lo with output
    float a = __ldg(&cosX[(size_t)tg[s_hi] * PP + p]);
    #pragma unroll 5
    for (int s = s_hi; s >= s_lo; s--) {
        float a_next = (s > s_lo)
            ? __ldg(&cosX[(size_t)tg[s - 1] * PP + p]) : 0.f;

        const float4* g4 = (const float4*)(Gs + s * JP + jb);
        float4 g0 = g4[0], g1 = g4[1];
        acc[0] += a * g0.x; acc[1] += a * g0.y;
        acc[2] += a * g0.z; acc[3] += a * g0.w;
        acc[4] += a * g1.x; acc[5] += a * g1.y;
        acc[6] += a * g1.z; acc[7] += a * g1.w;

        float part = 0.f;
        #pragma unroll
        for (int m = 0; m < 8; m++)
            part += fmaxf(acc[m], 0.f) * w2r[m];

        part += __shfl_xor_sync(0xffffffffu, part, 1);
        part += __shfl_xor_sync(0xffffffffu, part, 2);
        part += __shfl_xor_sync(0xffffffffu, part, 4);
        if (q == 0)
            out[(b * TT + s) * PP + p] = part + bias2;

        a = a_next;
    }
}

// ============================================================
// Launcher
// ============================================================
extern "C" void kernel_launch(void* const* d_in, const int* in_sizes, int n_in,
                              void* d_out, int out_size)
{
    const int   *tgt = nullptr, *cor = nullptr;
    const float *X = nullptr, *cosX = nullptr, *emb2 = nullptr, *Wk = nullptr;
    const float *Wr = nullptr, *bl = nullptr, *W1 = nullptr, *b1 = nullptr;
    const float *W2 = nullptr, *b2 = nullptr;

    int cnt1 = 0;
    for (int i = 0; i < n_in; i++) if (in_sizes[i] == 1) cnt1++;
    int seen1 = 0;

    for (int i = 0; i < n_in; i++) {
        int sz = in_sizes[i];
        const void* ptr = d_in[i];
        if (sz == BB * TT) {
            if (!tgt) tgt = (const int*)ptr; else cor = (const int*)ptr;
        } else if (sz == PP * PP)   cosX = (const float*)ptr;
        else if (sz == PP * D2)     X    = (const float*)ptr;
        else if (sz == D4 * D4)     Wk   = (const float*)ptr;
        else if (sz == UU * D4)     Wr   = (const float*)ptr;
        else if (sz == 2 * D4)      emb2 = (const float*)ptr;
        else if (sz == D4)          bl   = (const float*)ptr;
        else if (sz == 3 * UU * JJ) W1   = (const float*)ptr;
        else if (sz == JJ) {
            if (!b1) b1 = (const float*)ptr; else W2 = (const float*)ptr;
        } else if (sz == 1) {
            seen1++;
            if (seen1 == cnt1) b2 = (const float*)ptr;
        }
    }

    // 1) input projection (high-occupancy, MLP-16 version)
    k_zin<<<BB * TT, 1024>>>(tgt, cor, X, emb2, Wk, bl);
    // 2) LSTM (blocks 0-1) overlapped with XW1 GEMM (blocks 2..161)
    k_work<<<2 + NXW, 256>>>(tgt, X, Wr, W1, b1);
    // 3) fused suffix-sum + MLP + octet reduce; (160 p, 2 chunk, 2 b)
    k_main<<<dim3(160, 2, 2), 256>>>(tgt, cosX, W2, b2, (float*)d_out);
}